// round 2
// baseline (speedup 1.0000x reference)
#include <cuda_runtime.h>
#include <cstdint>

// ---------------------------------------------------------------------------
// Problem constants
// ---------------------------------------------------------------------------
#define SEQ   2048
#define DM    4096
#define NH    32
#define NKV   8
#define HD    128
#define KVD   (NKV * HD)   // 1024

// ---------------------------------------------------------------------------
// Scratch (device globals: allocation-free rule)
// ---------------------------------------------------------------------------
__device__ float g_xq[SEQ * DM];                     // 32 MB
__device__ float g_xk[SEQ * KVD];                    //  8 MB
__device__ float g_xv[SEQ * KVD];                    //  8 MB
__device__ float g_vt[NKV * HD * SEQ];               //  8 MB  V transposed per kv-head: [kv][d][s]
__device__ float g_sc[(size_t)NH * SEQ * SEQ];       // 512 MB scores / probs
__device__ float g_att[SEQ * DM];                    // 32 MB  attention output (b,s,h*d)

// Canonical int8 packed weights (repacked from whatever dtype the harness gives)
__device__ int8_t g_wq8[NH  * HD * DM / 2];          // 8.4 MB
__device__ int8_t g_wk8[NKV * HD * DM / 2];          // 2.1 MB
__device__ int8_t g_wv8[NKV * HD * DM / 2];          // 2.1 MB
__device__ int8_t g_wo8[DM * NH * HD / 2];           // 8.4 MB
__device__ int    g_mode;                            // 0 = raw int8 stream, 1 = int32-per-byte

// ---------------------------------------------------------------------------
// Probe: decide whether weight buffers are a raw int8 byte stream or one
// packed byte per int32 element. If the harness promoted int8 -> int32, every
// 32-bit word holds a sign-extended byte value in [-128, 127]. A raw packed
// byte stream read as int32 words gives 4 random bytes per word; the chance
// that 256 consecutive words all land in [-128, 127] is ~(2/256)^256 ~= 0.
// Deterministic: same input bytes -> same mode on every call.
// ---------------------------------------------------------------------------
__global__ void probe_mode(const int* __restrict__ w)
{
    if (threadIdx.x == 0 && blockIdx.x == 0) {
        int ok = 0;
        for (int i = 0; i < 256; i++) {
            const int v = w[i];
            if (v >= -128 && v <= 127) ok++;
        }
        g_mode = (ok >= 250) ? 1 : 0;
    }
}

// Repack weights into canonical int8 stream according to g_mode.
__global__ __launch_bounds__(256) void repack_w(
    const void* __restrict__ in, int8_t* __restrict__ out, long n)
{
    const int mode = g_mode;
    const long stride = (long)gridDim.x * blockDim.x;
    for (long i = (long)blockIdx.x * blockDim.x + threadIdx.x; i < n; i += stride) {
        if (mode) out[i] = (int8_t)((const int*)in)[i];
        else      out[i] = ((const int8_t*)in)[i];
    }
}

// ---------------------------------------------------------------------------
// GEMM with fused Q4_0 dequant:  C[m][n] = sum_k A[m][k] * W[n][k]
// W packed Q4_0: flat index f = n*K + k; packed row r = f/128 holds 64 bytes;
// f%128 < 64 -> high nibble of byte (f%64), else low nibble of byte (f%64).
// scale index = f/64.
// Tiles: BM=BN=128, BK=32, 256 threads, 8x8 microtile.
// ---------------------------------------------------------------------------
__global__ __launch_bounds__(256) void gemm_q40(
    const float* __restrict__ A, const int8_t* __restrict__ Wp,
    const float* __restrict__ Sc, float* __restrict__ C,
    int M, int N, int K, int lda, int ldc)
{
    __shared__ float As[32][128];
    __shared__ float Bs[32][128];

    const int m0  = blockIdx.y * 128;
    const int n0  = blockIdx.x * 128;
    const int tid = threadIdx.x;
    const int tx  = tid & 15;
    const int ty  = tid >> 4;

    const int arow  = tid >> 3;          // 0..31
    const int acol4 = (tid & 7) * 4;     // 0,4,...,28
    const int bn = tid >> 1;             // 0..127
    const int bj = (tid & 1) * 16;       // 0 or 16

    float acc[8][8];
#pragma unroll
    for (int i = 0; i < 8; i++)
#pragma unroll
        for (int j = 0; j < 8; j++) acc[i][j] = 0.0f;

    for (int k0 = 0; k0 < K; k0 += 32) {
        // ---- load A tile (transposed into smem) ----
#pragma unroll
        for (int it = 0; it < 4; it++) {
            const int m = m0 + arow + it * 32;
            const float4 v = *(const float4*)(A + (size_t)m * lda + k0 + acol4);
            As[acol4 + 0][arow + it * 32] = v.x;
            As[acol4 + 1][arow + it * 32] = v.y;
            As[acol4 + 2][arow + it * 32] = v.z;
            As[acol4 + 3][arow + it * 32] = v.w;
        }
        // ---- dequantize B tile ----
        {
            const int n = n0 + bn;
            const long f0 = (long)n * K + k0;        // K%128==0 -> f0%128 == k0%128
            const float s = Sc[f0 >> 6];
            const long r  = f0 >> 7;
            const int  q  = (int)(f0 & 127);         // 0,32,64,96
            const bool msb = (q < 64);
            const int8_t* bp = Wp + r * 64 + (q & 63) + bj;   // 16B aligned
            int4 raw = *(const int4*)bp;
            const int8_t* rb = (const int8_t*)&raw;
#pragma unroll
            for (int j = 0; j < 16; j++) {
                int8_t b = rb[j];
                int v = msb ? (b >> 4) : (((int8_t)(b << 4)) >> 4);
                Bs[bj + j][bn] = (float)v * s;
            }
        }
        __syncthreads();

#pragma unroll
        for (int k = 0; k < 32; k++) {
            float a[8], b[8];
            *(float4*)&a[0] = *(const float4*)&As[k][ty * 8];
            *(float4*)&a[4] = *(const float4*)&As[k][ty * 8 + 4];
            *(float4*)&b[0] = *(const float4*)&Bs[k][tx * 8];
            *(float4*)&b[4] = *(const float4*)&Bs[k][tx * 8 + 4];
#pragma unroll
            for (int i = 0; i < 8; i++)
#pragma unroll
                for (int j = 0; j < 8; j++)
                    acc[i][j] += a[i] * b[j];
        }
        __syncthreads();
    }

#pragma unroll
    for (int i = 0; i < 8; i++) {
        float* cp = C + (size_t)(m0 + ty * 8 + i) * ldc + n0 + tx * 8;
        *(float4*)cp       = make_float4(acc[i][0], acc[i][1], acc[i][2], acc[i][3]);
        *(float4*)(cp + 4) = make_float4(acc[i][4], acc[i][5], acc[i][6], acc[i][7]);
    }
}

// ---------------------------------------------------------------------------
// Generic fp32 NT GEMM with per-head offsets and causal handling.
//   C[m][n] = alpha * sum_k A[m*lda + k] * B[n*ldb + k]
// head h = blockIdx.z; A += h*a_hs, B += (h/b_div)*b_hs, C += h*c_hs.
// causal==1 : skip block entirely if n0 > m0+127   (QK^T upper triangle)
// causal==2 : limit K to m0+128                    (PV: probs are 0 beyond)
// ---------------------------------------------------------------------------
__global__ __launch_bounds__(256) void gemm_nt(
    const float* __restrict__ Ab, const float* __restrict__ Bb,
    float* __restrict__ Cb,
    int M, int N, int K, int lda, int ldb, int ldc,
    long a_hs, long b_hs, int b_div, long c_hs,
    float alpha, int causal)
{
    const int h = blockIdx.z;
    const float* A = Ab + (long)h * a_hs;
    const float* B = Bb + (long)(h / b_div) * b_hs;
    float* C = Cb + (long)h * c_hs;

    const int m0 = blockIdx.y * 128;
    const int n0 = blockIdx.x * 128;
    if (causal == 1 && n0 > m0 + 127) return;
    int kmax = K;
    if (causal == 2) kmax = min(K, m0 + 128);

    __shared__ float As[32][128];
    __shared__ float Bs[32][128];

    const int tid = threadIdx.x;
    const int tx  = tid & 15;
    const int ty  = tid >> 4;
    const int lrow  = tid >> 3;
    const int lcol4 = (tid & 7) * 4;

    float acc[8][8];
#pragma unroll
    for (int i = 0; i < 8; i++)
#pragma unroll
        for (int j = 0; j < 8; j++) acc[i][j] = 0.0f;

    for (int k0 = 0; k0 < kmax; k0 += 32) {
#pragma unroll
        for (int it = 0; it < 4; it++) {
            const int m = m0 + lrow + it * 32;
            const float4 v = *(const float4*)(A + (size_t)m * lda + k0 + lcol4);
            As[lcol4 + 0][lrow + it * 32] = v.x;
            As[lcol4 + 1][lrow + it * 32] = v.y;
            As[lcol4 + 2][lrow + it * 32] = v.z;
            As[lcol4 + 3][lrow + it * 32] = v.w;
        }
#pragma unroll
        for (int it = 0; it < 4; it++) {
            const int n = n0 + lrow + it * 32;
            const float4 v = *(const float4*)(B + (size_t)n * ldb + k0 + lcol4);
            Bs[lcol4 + 0][lrow + it * 32] = v.x;
            Bs[lcol4 + 1][lrow + it * 32] = v.y;
            Bs[lcol4 + 2][lrow + it * 32] = v.z;
            Bs[lcol4 + 3][lrow + it * 32] = v.w;
        }
        __syncthreads();

#pragma unroll
        for (int k = 0; k < 32; k++) {
            float a[8], b[8];
            *(float4*)&a[0] = *(const float4*)&As[k][ty * 8];
            *(float4*)&a[4] = *(const float4*)&As[k][ty * 8 + 4];
            *(float4*)&b[0] = *(const float4*)&Bs[k][tx * 8];
            *(float4*)&b[4] = *(const float4*)&Bs[k][tx * 8 + 4];
#pragma unroll
            for (int i = 0; i < 8; i++)
#pragma unroll
                for (int j = 0; j < 8; j++)
                    acc[i][j] += a[i] * b[j];
        }
        __syncthreads();
    }

#pragma unroll
    for (int i = 0; i < 8; i++) {
        float* cp = C + (size_t)(m0 + ty * 8 + i) * ldc + n0 + tx * 8;
        *(float4*)cp       = make_float4(acc[i][0] * alpha, acc[i][1] * alpha,
                                         acc[i][2] * alpha, acc[i][3] * alpha);
        *(float4*)(cp + 4) = make_float4(acc[i][4] * alpha, acc[i][5] * alpha,
                                         acc[i][6] * alpha, acc[i][7] * alpha);
    }
}

// ---------------------------------------------------------------------------
// RoPE (rotate-half) in place on x laid out [SEQ, nheads, HD].
// ---------------------------------------------------------------------------
__global__ __launch_bounds__(256) void rope_kernel(
    float* __restrict__ x, const float* __restrict__ cosb,
    const float* __restrict__ sinb, int nheads)
{
    const long total = (long)SEQ * nheads * 64;
    long idx = (long)blockIdx.x * blockDim.x + threadIdx.x;
    if (idx >= total) return;
    const int d = (int)(idx & 63);
    const int h = (int)((idx >> 6) % nheads);
    const int s = (int)(idx / ((long)64 * nheads));
    float* p = x + (size_t)s * nheads * HD + h * HD + d;
    const float c  = cosb[s * 64 + d];
    const float sn = sinb[s * 64 + d];
    const float lo = p[0];
    const float hi = p[64];
    p[0]  = lo * c - hi * sn;
    p[64] = hi * c + lo * sn;
}

// ---------------------------------------------------------------------------
// Transpose V: vt[kv][d][s] = xv[s][kv*HD + d]
// ---------------------------------------------------------------------------
__global__ __launch_bounds__(256) void vtrans_kernel(
    const float* __restrict__ xv, float* __restrict__ vt)
{
    const long total = (long)NKV * HD * SEQ;
    long idx = (long)blockIdx.x * blockDim.x + threadIdx.x;
    if (idx >= total) return;
    const int s  = (int)(idx % SEQ);
    const int d  = (int)((idx / SEQ) % HD);
    const int kv = (int)(idx / ((long)SEQ * HD));
    vt[idx] = xv[(size_t)s * KVD + kv * HD + d];
}

// ---------------------------------------------------------------------------
// Causal row softmax in place. One block (128 threads) per (head,row).
// ---------------------------------------------------------------------------
__global__ __launch_bounds__(128) void softmax_causal(float* __restrict__ sc)
{
    const int row = blockIdx.x;           // h*SEQ + q
    const int q   = row & (SEQ - 1);
    float* p = sc + (size_t)row * SEQ;
    const int len  = q + 1;
    const int zend = ((q >> 7) + 1) << 7;
    const int tid  = threadIdx.x;

    __shared__ float red[4];

    float m = -1e30f;
    for (int k = tid; k < len; k += 128) m = fmaxf(m, p[k]);
#pragma unroll
    for (int o = 16; o > 0; o >>= 1) m = fmaxf(m, __shfl_xor_sync(0xffffffffu, m, o));
    if ((tid & 31) == 0) red[tid >> 5] = m;
    __syncthreads();
    m = fmaxf(fmaxf(red[0], red[1]), fmaxf(red[2], red[3]));
    __syncthreads();

    float sum = 0.0f;
    for (int k = tid; k < len; k += 128) {
        const float e = __expf(p[k] - m);
        p[k] = e;
        sum += e;
    }
#pragma unroll
    for (int o = 16; o > 0; o >>= 1) sum += __shfl_xor_sync(0xffffffffu, sum, o);
    if ((tid & 31) == 0) red[tid >> 5] = sum;
    __syncthreads();
    sum = red[0] + red[1] + red[2] + red[3];

    const float inv = 1.0f / sum;
    for (int k = tid; k < len; k += 128) p[k] *= inv;
    for (int k = len + tid; k < zend; k += 128) p[k] = 0.0f;
}

// ---------------------------------------------------------------------------
// Launch
// ---------------------------------------------------------------------------
extern "C" void kernel_launch(void* const* d_in, const int* in_sizes, int n_in,
                              void* d_out, int out_size)
{
    (void)in_sizes; (void)n_in; (void)out_size;
    const float* x    = (const float*)d_in[0];
    const void*  wq   = d_in[1];
    const float* sq   = (const float*)d_in[2];
    const void*  wk   = d_in[3];
    const float* sk   = (const float*)d_in[4];
    const void*  wv   = d_in[5];
    const float* sv   = (const float*)d_in[6];
    const void*  wo   = d_in[7];
    const float* so   = (const float*)d_in[8];
    const float* cosb = (const float*)d_in[9];
    const float* sinb = (const float*)d_in[10];
    float* out = (float*)d_out;

    float *xq, *xk, *xv, *vt, *sc, *att;
    int8_t *wq8, *wk8, *wv8, *wo8;
    cudaGetSymbolAddress((void**)&xq,  g_xq);
    cudaGetSymbolAddress((void**)&xk,  g_xk);
    cudaGetSymbolAddress((void**)&xv,  g_xv);
    cudaGetSymbolAddress((void**)&vt,  g_vt);
    cudaGetSymbolAddress((void**)&sc,  g_sc);
    cudaGetSymbolAddress((void**)&att, g_att);
    cudaGetSymbolAddress((void**)&wq8, g_wq8);
    cudaGetSymbolAddress((void**)&wk8, g_wk8);
    cudaGetSymbolAddress((void**)&wv8, g_wv8);
    cudaGetSymbolAddress((void**)&wo8, g_wo8);

    const dim3 blk(256);

    // 0) detect weight dtype layout, repack to canonical int8
    probe_mode<<<1, 32>>>((const int*)wq);
    const long nq = (long)NH  * HD * DM / 2;
    const long nk = (long)NKV * HD * DM / 2;
    repack_w<<<1024, blk>>>(wq, wq8, nq);
    repack_w<<<1024, blk>>>(wk, wk8, nk);
    repack_w<<<1024, blk>>>(wv, wv8, nk);
    repack_w<<<1024, blk>>>(wo, wo8, nq);

    // 1) QKV projections (fused Q4_0 dequant)
    gemm_q40<<<dim3(DM  / 128, SEQ / 128), blk>>>(x, wq8, sq, xq, SEQ, DM,  DM, DM, DM);
    gemm_q40<<<dim3(KVD / 128, SEQ / 128), blk>>>(x, wk8, sk, xk, SEQ, KVD, DM, DM, KVD);
    gemm_q40<<<dim3(KVD / 128, SEQ / 128), blk>>>(x, wv8, sv, xv, SEQ, KVD, DM, DM, KVD);

    // 2) RoPE on q and k
    rope_kernel<<<(SEQ * NH  * 64 + 255) / 256, blk>>>(xq, cosb, sinb, NH);
    rope_kernel<<<(SEQ * NKV * 64 + 255) / 256, blk>>>(xk, cosb, sinb, NKV);

    // 3) Transpose V for the PV gemm
    vtrans_kernel<<<(NKV * HD * SEQ + 255) / 256, blk>>>(xv, vt);

    // 4) scores = Q K^T / sqrt(HD), lower-triangular blocks only
    gemm_nt<<<dim3(SEQ / 128, SEQ / 128, NH), blk>>>(
        xq, xk, sc,
        SEQ, SEQ, HD, DM, KVD, SEQ,
        (long)HD, (long)HD, NH / NKV, (long)SEQ * SEQ,
        0.08838834764831843f, /*causal=*/1);

    // 5) causal softmax (in place)
    softmax_causal<<<NH * SEQ, 128>>>(sc);

    // 6) att = P V
    gemm_nt<<<dim3(HD / 128, SEQ / 128, NH), blk>>>(
        sc, vt, att,
        SEQ, HD, SEQ, SEQ, SEQ, DM,
        (long)SEQ * SEQ, (long)HD * SEQ, NH / NKV, (long)HD,
        1.0f, /*causal=*/2);

    // 7) output projection (fused Q4_0 dequant)
    gemm_q40<<<dim3(DM / 128, SEQ / 128), blk>>>(att, wo8, so, out, SEQ, DM, DM, DM, DM);
}

// round 4
// speedup vs baseline: 1.7004x; 1.7004x over previous
#include <cuda_runtime.h>
#include <cuda_bf16.h>
#include <cstdint>

// ---------------------------------------------------------------------------
// Problem constants
// ---------------------------------------------------------------------------
#define SEQ   2048
#define DM    4096
#define NH    32
#define NKV   8
#define HD    128
#define KVD   (NKV * HD)   // 1024

typedef __nv_bfloat16 bf16;

// ---------------------------------------------------------------------------
// Device-global scratch (allocation-free rule)
// ---------------------------------------------------------------------------
__device__ float g_xq[SEQ * DM];
__device__ float g_xk[SEQ * KVD];
__device__ float g_xv[SEQ * KVD];
__device__ float g_sc[(size_t)NH * SEQ * SEQ];     // fp32 scores
__device__ float g_att[SEQ * DM];

// bf16 hi/lo split operands
__device__ __align__(16) bf16 g_xh [SEQ * DM],  g_xl [SEQ * DM];
__device__ __align__(16) bf16 g_qh [SEQ * DM],  g_ql [SEQ * DM];
__device__ __align__(16) bf16 g_kh [SEQ * KVD], g_kl [SEQ * KVD];
__device__ __align__(16) bf16 g_vth[NKV * HD * SEQ], g_vtl[NKV * HD * SEQ];
__device__ __align__(16) bf16 g_ath[SEQ * DM],  g_atl[SEQ * DM];
__device__ __align__(16) bf16 g_ph [(size_t)NH * SEQ * SEQ];
__device__ __align__(16) bf16 g_pl [(size_t)NH * SEQ * SEQ];
__device__ __align__(16) bf16 g_wqh[DM * DM],   g_wql[DM * DM];
__device__ __align__(16) bf16 g_wkh[KVD * DM],  g_wkl[KVD * DM];
__device__ __align__(16) bf16 g_wvh[KVD * DM],  g_wvl[KVD * DM];
__device__ __align__(16) bf16 g_woh[DM * DM],   g_wol[DM * DM];

// canonical int8 packed weights
__device__ int8_t g_wq8[DM * DM / 2];
__device__ int8_t g_wk8[KVD * DM / 2];
__device__ int8_t g_wv8[KVD * DM / 2];
__device__ int8_t g_wo8[DM * DM / 2];
__device__ int    g_mode;

// ---------------------------------------------------------------------------
// PTX helpers (base sm_103 ISA only: cp.async / ldmatrix / mma.sync)
// ---------------------------------------------------------------------------
__device__ __forceinline__ uint32_t smem_u32(const void* p) {
    uint32_t a;
    asm("{ .reg .u64 t; cvta.to.shared.u64 t, %1; cvt.u32.u64 %0, t; }" : "=r"(a) : "l"(p));
    return a;
}
__device__ __forceinline__ void cp16(uint32_t dst, const void* src) {
    asm volatile("cp.async.cg.shared.global [%0], [%1], 16;" :: "r"(dst), "l"(src) : "memory");
}
__device__ __forceinline__ void cp_commit() {
    asm volatile("cp.async.commit_group;" ::: "memory");
}
template <int N>
__device__ __forceinline__ void cp_wait() {
    asm volatile("cp.async.wait_group %0;" :: "n"(N) : "memory");
}
__device__ __forceinline__ void ldm_x4(uint32_t* r, uint32_t addr) {
    asm volatile("ldmatrix.sync.aligned.m8n8.x4.shared.b16 {%0,%1,%2,%3}, [%4];"
                 : "=r"(r[0]), "=r"(r[1]), "=r"(r[2]), "=r"(r[3]) : "r"(addr));
}
__device__ __forceinline__ void mma16816(float* d, const uint32_t* a,
                                         uint32_t b0, uint32_t b1) {
    asm volatile(
        "mma.sync.aligned.m16n8k16.row.col.f32.bf16.bf16.f32 "
        "{%0,%1,%2,%3}, {%4,%5,%6,%7}, {%8,%9}, {%0,%1,%2,%3};"
        : "+f"(d[0]), "+f"(d[1]), "+f"(d[2]), "+f"(d[3])
        : "r"(a[0]), "r"(a[1]), "r"(a[2]), "r"(a[3]), "r"(b0), "r"(b1));
}

// Permuted conflict-free smem layout for one 128x32 bf16 tile (8 KB):
// atom = 8 rows x 16B (one k8 chunk), stored contiguously (128 B).
// offset(row, kc) = ((row/8)*4 + kc)*128 + (row%8)*16,  kc in 0..3 (k8 chunks)
__device__ __forceinline__ uint32_t tile_off(int row, int kc) {
    return (uint32_t)((((row >> 3) * 4 + kc) << 7) + ((row & 7) << 4));
}

// ---------------------------------------------------------------------------
// Probe + repack (dtype-robust weight ingestion, proven in round 2)
// ---------------------------------------------------------------------------
__global__ void probe_mode(const int* __restrict__ w)
{
    if (threadIdx.x == 0 && blockIdx.x == 0) {
        int ok = 0;
        for (int i = 0; i < 256; i++) {
            const int v = w[i];
            if (v >= -128 && v <= 127) ok++;
        }
        g_mode = (ok >= 250) ? 1 : 0;
    }
}
__global__ __launch_bounds__(256) void repack_w(
    const void* __restrict__ in, int8_t* __restrict__ out, long n)
{
    const int mode = g_mode;
    const long stride = (long)gridDim.x * blockDim.x;
    for (long i = (long)blockIdx.x * blockDim.x + threadIdx.x; i < n; i += stride) {
        if (mode) out[i] = (int8_t)((const int*)in)[i];
        else      out[i] = ((const int8_t*)in)[i];
    }
}

// ---------------------------------------------------------------------------
// Dequant Q4_0 + split into bf16 hi/lo.
// ---------------------------------------------------------------------------
__global__ __launch_bounds__(256) void dequant_split_w(
    const int8_t* __restrict__ w8, const float* __restrict__ sc,
    bf16* __restrict__ wh, bf16* __restrict__ wl, long n)
{
    const long stride = (long)gridDim.x * blockDim.x;
    for (long f = (long)blockIdx.x * blockDim.x + threadIdx.x; f < n; f += stride) {
        const long r = f >> 7;
        const int  q = (int)(f & 127);
        const int8_t b = w8[r * 64 + (q & 63)];
        const int nib = (q < 64) ? (b >> 4) : (((int8_t)(b << 4)) >> 4);
        const float v = (float)nib * sc[f >> 6];
        const bf16 hi = __float2bfloat16(v);
        wh[f] = hi;
        wl[f] = __float2bfloat16(v - __bfloat162float(hi));
    }
}

// Generic fp32 -> bf16 hi/lo split
__global__ __launch_bounds__(256) void split_f32(
    const float* __restrict__ src, bf16* __restrict__ hi, bf16* __restrict__ lo, long n)
{
    const long stride = (long)gridDim.x * blockDim.x;
    for (long i = (long)blockIdx.x * blockDim.x + threadIdx.x; i < n; i += stride) {
        const float v = src[i];
        const bf16 h = __float2bfloat16(v);
        hi[i] = h;
        lo[i] = __float2bfloat16(v - __bfloat162float(h));
    }
}

// ---------------------------------------------------------------------------
// RoPE (rotate-half) + optional scale + bf16 split.  x laid out [S, nh, HD].
// ---------------------------------------------------------------------------
__global__ __launch_bounds__(256) void rope_split(
    const float* __restrict__ x, const float* __restrict__ cosb,
    const float* __restrict__ sinb, bf16* __restrict__ oh, bf16* __restrict__ ol,
    int nheads, float scale)
{
    const long total = (long)SEQ * nheads * 64;
    long idx = (long)blockIdx.x * blockDim.x + threadIdx.x;
    if (idx >= total) return;
    const int d = (int)(idx & 63);
    const int h = (int)((idx >> 6) % nheads);
    const int s = (int)(idx / ((long)64 * nheads));
    const size_t base = (size_t)s * nheads * HD + h * HD + d;
    const float c  = cosb[s * 64 + d];
    const float sn = sinb[s * 64 + d];
    const float lo = x[base];
    const float hi = x[base + 64];
    const float r0 = (lo * c - hi * sn) * scale;
    const float r1 = (hi * c + lo * sn) * scale;
    bf16 h0 = __float2bfloat16(r0);
    bf16 h1 = __float2bfloat16(r1);
    oh[base]      = h0;
    ol[base]      = __float2bfloat16(r0 - __bfloat162float(h0));
    oh[base + 64] = h1;
    ol[base + 64] = __float2bfloat16(r1 - __bfloat162float(h1));
}

// ---------------------------------------------------------------------------
// Transpose V + split: vt[kv][d][s] = xv[s][kv*HD + d]
// ---------------------------------------------------------------------------
__global__ __launch_bounds__(256) void vtrans_split(
    const float* __restrict__ xv, bf16* __restrict__ vh, bf16* __restrict__ vl)
{
    const long total = (long)NKV * HD * SEQ;
    long idx = (long)blockIdx.x * blockDim.x + threadIdx.x;
    if (idx >= total) return;
    const int s  = (int)(idx % SEQ);
    const int d  = (int)((idx / SEQ) % HD);
    const int kv = (int)(idx / ((long)SEQ * HD));
    const float v = xv[(size_t)s * KVD + kv * HD + d];
    const bf16 h = __float2bfloat16(v);
    vh[idx] = h;
    vl[idx] = __float2bfloat16(v - __bfloat162float(h));
}

// ---------------------------------------------------------------------------
// Causal row softmax: fp32 scores -> bf16 hi/lo probs, zero-filled to the
// next 128 boundary (exactly the region the PV GEMM reads).
// ---------------------------------------------------------------------------
__global__ __launch_bounds__(128) void softmax_split(
    const float* __restrict__ sc, bf16* __restrict__ ph, bf16* __restrict__ pl)
{
    const int row = blockIdx.x;          // h*SEQ + q
    const int q   = row & (SEQ - 1);
    const float* p = sc + (size_t)row * SEQ;
    bf16* oh = ph + (size_t)row * SEQ;
    bf16* ol = pl + (size_t)row * SEQ;
    const int len  = q + 1;
    const int zend = ((q >> 7) + 1) << 7;
    const int tid  = threadIdx.x;

    __shared__ float red[4];

    float m = -1e30f;
    for (int k = tid; k < len; k += 128) m = fmaxf(m, p[k]);
#pragma unroll
    for (int o = 16; o > 0; o >>= 1) m = fmaxf(m, __shfl_xor_sync(0xffffffffu, m, o));
    if ((tid & 31) == 0) red[tid >> 5] = m;
    __syncthreads();
    m = fmaxf(fmaxf(red[0], red[1]), fmaxf(red[2], red[3]));
    __syncthreads();

    float sum = 0.0f;
    for (int k = tid; k < len; k += 128) sum += __expf(p[k] - m);
#pragma unroll
    for (int o = 16; o > 0; o >>= 1) sum += __shfl_xor_sync(0xffffffffu, sum, o);
    if ((tid & 31) == 0) red[tid >> 5] = sum;
    __syncthreads();
    sum = red[0] + red[1] + red[2] + red[3];

    const float inv = 1.0f / sum;
    for (int k = tid; k < len; k += 128) {
        const float v = __expf(p[k] - m) * inv;
        const bf16 h = __float2bfloat16(v);
        oh[k] = h;
        ol[k] = __float2bfloat16(v - __bfloat162float(h));
    }
    const bf16 z = __float2bfloat16(0.0f);
    for (int k = len + tid; k < zend; k += 128) { oh[k] = z; ol[k] = z; }
}

// ---------------------------------------------------------------------------
// mma.sync bf16 split-precision NT GEMM.
//   C[m][n] = alpha * sum_k (Ah+Al)[m][k] * (Bh+Bl)[n][k]   (3-product split)
// CTA tile 128x128, BK=32, 2-stage cp.async pipeline.
// 8 warps: warp_m = wid&3 (32 rows each), warp_n = wid>>2 (64 cols each).
// head h = blockIdx.z; A += h*a_hs, B += (h/b_div)*b_hs, C += h*c_hs.
// causal==1: skip tile if n0 > m0+127.  causal==2: K limited to m0+128.
// Requires rows%128==0, K%32==0 (all uses satisfy this).
// ---------------------------------------------------------------------------
#define GS_TILE_BYTES  8192                 // one 128x32 bf16 tile
#define GS_STAGE_BYTES (4 * GS_TILE_BYTES)  // Ah, Al, Bh, Bl
#define GS_SMEM_TOTAL  (2 * GS_STAGE_BYTES) // 64 KB

__global__ __launch_bounds__(256, 2) void gemm_bf16s(
    const bf16* __restrict__ Ah, const bf16* __restrict__ Al,
    const bf16* __restrict__ Bh, const bf16* __restrict__ Bl,
    float* __restrict__ Cb,
    int K, int lda, int ldb, int ldc,
    long a_hs, long b_hs, int b_div, long c_hs,
    float alpha, int causal)
{
    const int m0 = blockIdx.y * 128;
    const int n0 = blockIdx.x * 128;
    if (causal == 1 && n0 > m0 + 127) return;

    extern __shared__ char smem[];
    const uint32_t sb = smem_u32(smem);
    const int tid  = threadIdx.x;
    const int wid  = tid >> 5;
    const int lane = tid & 31;
    const int h = blockIdx.z;

    const bf16* ah = Ah + (long)h * a_hs;
    const bf16* al = Al + (long)h * a_hs;
    const bf16* bh = Bh + (long)(h / b_div) * b_hs;
    const bf16* bl = Bl + (long)(h / b_div) * b_hs;
    float* C = Cb + (long)h * c_hs;

    const int kmax = (causal == 2) ? min(K, m0 + 128) : K;
    const int NC = kmax >> 5;

    const int wm = (wid & 3) * 32;   // warp m-offset in tile
    const int wn = (wid >> 2) * 64;  // warp n-offset in tile

    // loader mapping: each thread fills 2 x 16B chunks per operand array
    const int lrow = tid >> 1;             // 0..127
    const int lkc0 = (tid & 1) * 2;        // 0 or 2

    float acc[2][8][4];
#pragma unroll
    for (int i = 0; i < 2; i++)
#pragma unroll
        for (int j = 0; j < 8; j++)
#pragma unroll
            for (int v = 0; v < 4; v++) acc[i][j][v] = 0.0f;

    // ---- stage loader ----
    auto load_stage = [&](int c) {
        const int k0 = c << 5;
        const uint32_t st = sb + (uint32_t)(c & 1) * GS_STAGE_BYTES;
        const bf16* pa_h = ah + (size_t)(m0 + lrow) * lda + k0;
        const bf16* pa_l = al + (size_t)(m0 + lrow) * lda + k0;
        const bf16* pb_h = bh + (size_t)(n0 + lrow) * ldb + k0;
        const bf16* pb_l = bl + (size_t)(n0 + lrow) * ldb + k0;
#pragma unroll
        for (int i = 0; i < 2; i++) {
            const int kc = lkc0 + i;
            const uint32_t off = tile_off(lrow, kc);
            cp16(st + 0 * GS_TILE_BYTES + off, pa_h + kc * 8);
            cp16(st + 1 * GS_TILE_BYTES + off, pa_l + kc * 8);
            cp16(st + 2 * GS_TILE_BYTES + off, pb_h + kc * 8);
            cp16(st + 3 * GS_TILE_BYTES + off, pb_l + kc * 8);
        }
        cp_commit();
    };

    load_stage(0);

    for (int c = 0; c < NC; c++) {
        if (c + 1 < NC) { load_stage(c + 1); cp_wait<1>(); }
        else            { cp_wait<0>(); }
        __syncthreads();

        const uint32_t st = sb + (uint32_t)(c & 1) * GS_STAGE_BYTES;
        const int lrow16 = lane & 15;
        const int lhi    = lane >> 4;

#pragma unroll
        for (int kb2 = 0; kb2 < 2; kb2++) {         // k16 blocks within BK=32
            const int kcb = kb2 * 2;
            // A fragments: 2 m16 tiles, hi + lo
            uint32_t afh[2][4], afl[2][4];
#pragma unroll
            for (int mt = 0; mt < 2; mt++) {
                const uint32_t off = tile_off(wm + mt * 16 + lrow16, kcb + lhi);
                ldm_x4(afh[mt], st + 0 * GS_TILE_BYTES + off);
                ldm_x4(afl[mt], st + 1 * GS_TILE_BYTES + off);
            }
#pragma unroll
            for (int g = 0; g < 4; g++) {           // 4 n16 groups in warp's 64 cols
                const uint32_t boff = tile_off(wn + g * 16 + lrow16, kcb + lhi);
                uint32_t bhf[4], blf[4];
                ldm_x4(bhf, st + 2 * GS_TILE_BYTES + boff);
                ldm_x4(blf, st + 3 * GS_TILE_BYTES + boff);
#pragma unroll
                for (int mt = 0; mt < 2; mt++) {
#pragma unroll
                    for (int sub = 0; sub < 2; sub++) {
                        float* d = acc[mt][g * 2 + sub];
                        mma16816(d, afh[mt], bhf[sub], bhf[sub + 2]); // hi*hi
                        mma16816(d, afh[mt], blf[sub], blf[sub + 2]); // hi*lo
                        mma16816(d, afl[mt], bhf[sub], bhf[sub + 2]); // lo*hi
                    }
                }
            }
        }
        __syncthreads();
    }

    // ---- epilogue ----
#pragma unroll
    for (int mt = 0; mt < 2; mt++) {
        const int mrow = m0 + wm + mt * 16 + (lane >> 2);
#pragma unroll
        for (int g = 0; g < 4; g++) {
#pragma unroll
            for (int sub = 0; sub < 2; sub++) {
                const float* d = acc[mt][g * 2 + sub];
                const int n = n0 + wn + g * 16 + sub * 8 + (lane & 3) * 2;
                float2 v0 = make_float2(d[0] * alpha, d[1] * alpha);
                float2 v1 = make_float2(d[2] * alpha, d[3] * alpha);
                *(float2*)(C + (size_t)mrow * ldc + n)       = v0;
                *(float2*)(C + (size_t)(mrow + 8) * ldc + n) = v1;
            }
        }
    }
}

// ---------------------------------------------------------------------------
// Launch
// ---------------------------------------------------------------------------
extern "C" void kernel_launch(void* const* d_in, const int* in_sizes, int n_in,
                              void* d_out, int out_size)
{
    (void)in_sizes; (void)n_in; (void)out_size;
    const float* x    = (const float*)d_in[0];
    const void*  wq   = d_in[1];
    const float* sq   = (const float*)d_in[2];
    const void*  wk   = d_in[3];
    const float* sk   = (const float*)d_in[4];
    const void*  wv   = d_in[5];
    const float* sv   = (const float*)d_in[6];
    const void*  wo   = d_in[7];
    const float* so   = (const float*)d_in[8];
    const float* cosb = (const float*)d_in[9];
    const float* sinb = (const float*)d_in[10];
    float* out = (float*)d_out;

    float *xq, *xk, *xv, *sc, *att;
    bf16 *xh, *xl, *qh, *ql, *kh, *kl, *vth, *vtl, *ath, *atl, *ph, *pl;
    bf16 *wqh, *wql, *wkh, *wkl, *wvh, *wvl, *woh, *wol;
    int8_t *wq8, *wk8, *wv8, *wo8;

    cudaGetSymbolAddress((void**)&xq,  g_xq);
    cudaGetSymbolAddress((void**)&xk,  g_xk);
    cudaGetSymbolAddress((void**)&xv,  g_xv);
    cudaGetSymbolAddress((void**)&sc,  g_sc);
    cudaGetSymbolAddress((void**)&att, g_att);
    cudaGetSymbolAddress((void**)&xh,  g_xh);   cudaGetSymbolAddress((void**)&xl,  g_xl);
    cudaGetSymbolAddress((void**)&qh,  g_qh);   cudaGetSymbolAddress((void**)&ql,  g_ql);
    cudaGetSymbolAddress((void**)&kh,  g_kh);   cudaGetSymbolAddress((void**)&kl,  g_kl);
    cudaGetSymbolAddress((void**)&vth, g_vth);  cudaGetSymbolAddress((void**)&vtl, g_vtl);
    cudaGetSymbolAddress((void**)&ath, g_ath);  cudaGetSymbolAddress((void**)&atl, g_atl);
    cudaGetSymbolAddress((void**)&ph,  g_ph);   cudaGetSymbolAddress((void**)&pl,  g_pl);
    cudaGetSymbolAddress((void**)&wqh, g_wqh);  cudaGetSymbolAddress((void**)&wql, g_wql);
    cudaGetSymbolAddress((void**)&wkh, g_wkh);  cudaGetSymbolAddress((void**)&wkl, g_wkl);
    cudaGetSymbolAddress((void**)&wvh, g_wvh);  cudaGetSymbolAddress((void**)&wvl, g_wvl);
    cudaGetSymbolAddress((void**)&woh, g_woh);  cudaGetSymbolAddress((void**)&wol, g_wol);
    cudaGetSymbolAddress((void**)&wq8, g_wq8);  cudaGetSymbolAddress((void**)&wk8, g_wk8);
    cudaGetSymbolAddress((void**)&wv8, g_wv8);  cudaGetSymbolAddress((void**)&wo8, g_wo8);

    cudaFuncSetAttribute(gemm_bf16s, cudaFuncAttributeMaxDynamicSharedMemorySize,
                         GS_SMEM_TOTAL);

    const dim3 blk(256);
    const long nq = (long)DM * DM / 2;
    const long nk = (long)KVD * DM / 2;

    // 0) ingest weights (dtype-robust) + dequant/split + split x
    probe_mode<<<1, 32>>>((const int*)wq);
    repack_w<<<1024, blk>>>(wq, wq8, nq);
    repack_w<<<1024, blk>>>(wk, wk8, nk);
    repack_w<<<1024, blk>>>(wv, wv8, nk);
    repack_w<<<1024, blk>>>(wo, wo8, nq);
    dequant_split_w<<<2048, blk>>>(wq8, sq, wqh, wql, (long)DM * DM);
    dequant_split_w<<<2048, blk>>>(wk8, sk, wkh, wkl, (long)KVD * DM);
    dequant_split_w<<<2048, blk>>>(wv8, sv, wvh, wvl, (long)KVD * DM);
    dequant_split_w<<<2048, blk>>>(wo8, so, woh, wol, (long)DM * DM);
    split_f32<<<2048, blk>>>(x, xh, xl, (long)SEQ * DM);

    // 1) QKV projections (tensor cores, split precision)
    gemm_bf16s<<<dim3(DM  / 128, SEQ / 128, 1), blk, GS_SMEM_TOTAL>>>(
        xh, xl, wqh, wql, xq, DM, DM, DM, DM, 0, 0, 1, 0, 1.0f, 0);
    gemm_bf16s<<<dim3(KVD / 128, SEQ / 128, 1), blk, GS_SMEM_TOTAL>>>(
        xh, xl, wkh, wkl, xk, DM, DM, DM, KVD, 0, 0, 1, 0, 1.0f, 0);
    gemm_bf16s<<<dim3(KVD / 128, SEQ / 128, 1), blk, GS_SMEM_TOTAL>>>(
        xh, xl, wvh, wvl, xv, DM, DM, DM, KVD, 0, 0, 1, 0, 1.0f, 0);

    // 2) RoPE + scale (q only) + split ; V transpose + split
    rope_split<<<(SEQ * NH  * 64 + 255) / 256, blk>>>(xq, cosb, sinb, qh, ql, NH,
                                                      0.08838834764831843f);
    rope_split<<<(SEQ * NKV * 64 + 255) / 256, blk>>>(xk, cosb, sinb, kh, kl, NKV, 1.0f);
    vtrans_split<<<(NKV * HD * SEQ + 255) / 256, blk>>>(xv, vth, vtl);

    // 3) scores = (q/sqrt(HD)) K^T   (lower-triangular tiles only)
    gemm_bf16s<<<dim3(SEQ / 128, SEQ / 128, NH), blk, GS_SMEM_TOTAL>>>(
        qh, ql, kh, kl, sc, HD, DM, KVD, SEQ,
        (long)HD, (long)HD, NH / NKV, (long)SEQ * SEQ, 1.0f, 1);

    // 4) causal softmax -> split probs
    softmax_split<<<NH * SEQ, 128>>>(sc, ph, pl);

    // 5) att = P V
    gemm_bf16s<<<dim3(HD / 128, SEQ / 128, NH), blk, GS_SMEM_TOTAL>>>(
        ph, pl, vth, vtl, att, SEQ, SEQ, SEQ, DM,
        (long)SEQ * SEQ, (long)HD * SEQ, NH / NKV, (long)HD, 1.0f, 2);

    // 6) output projection
    split_f32<<<2048, blk>>>(att, ath, atl, (long)SEQ * DM);
    gemm_bf16s<<<dim3(DM / 128, SEQ / 128, 1), blk, GS_SMEM_TOTAL>>>(
        ath, atl, woh, wol, out, DM, DM, DM, DM, 0, 0, 1, 0, 1.0f, 0);
}

// round 5
// speedup vs baseline: 1.7107x; 1.0060x over previous
#include <cuda_runtime.h>
#include <cuda_bf16.h>
#include <cstdint>

// ---------------------------------------------------------------------------
// Problem constants
// ---------------------------------------------------------------------------
#define SEQ   2048
#define DM    4096
#define NH    32
#define NKV   8
#define HD    128
#define KVD   (NKV * HD)   // 1024

typedef __nv_bfloat16 bf16;

// ---------------------------------------------------------------------------
// Device-global scratch (allocation-free rule)
// ---------------------------------------------------------------------------
__device__ float g_xq[SEQ * DM];
__device__ float g_xk[SEQ * KVD];
__device__ float g_xv[SEQ * KVD];
__device__ float g_sc[(size_t)NH * SEQ * SEQ];     // fp32 scores
__device__ float g_att[SEQ * DM];

// bf16 hi/lo split operands
__device__ __align__(16) bf16 g_xh [SEQ * DM],  g_xl [SEQ * DM];
__device__ __align__(16) bf16 g_qh [SEQ * DM],  g_ql [SEQ * DM];
__device__ __align__(16) bf16 g_kh [SEQ * KVD], g_kl [SEQ * KVD];
__device__ __align__(16) bf16 g_vth[NKV * HD * SEQ], g_vtl[NKV * HD * SEQ];
__device__ __align__(16) bf16 g_ath[SEQ * DM],  g_atl[SEQ * DM];
__device__ __align__(16) bf16 g_ph [(size_t)NH * SEQ * SEQ];
__device__ __align__(16) bf16 g_pl [(size_t)NH * SEQ * SEQ];
__device__ __align__(16) bf16 g_wqh[DM * DM],   g_wql[DM * DM];
__device__ __align__(16) bf16 g_wkh[KVD * DM],  g_wkl[KVD * DM];
__device__ __align__(16) bf16 g_wvh[KVD * DM],  g_wvl[KVD * DM];
__device__ __align__(16) bf16 g_woh[DM * DM],   g_wol[DM * DM];

// canonical int8 packed weights
__device__ int8_t g_wq8[DM * DM / 2];
__device__ int8_t g_wk8[KVD * DM / 2];
__device__ int8_t g_wv8[KVD * DM / 2];
__device__ int8_t g_wo8[DM * DM / 2];
__device__ int    g_mode;

// ---------------------------------------------------------------------------
// PTX helpers (base sm_103 ISA: cp.async / ldmatrix / mma.sync)
// ---------------------------------------------------------------------------
__device__ __forceinline__ uint32_t smem_u32(const void* p) {
    uint32_t a;
    asm("{ .reg .u64 t; cvta.to.shared.u64 t, %1; cvt.u32.u64 %0, t; }" : "=r"(a) : "l"(p));
    return a;
}
__device__ __forceinline__ void cp16(uint32_t dst, const void* src) {
    asm volatile("cp.async.cg.shared.global [%0], [%1], 16;" :: "r"(dst), "l"(src) : "memory");
}
__device__ __forceinline__ void cp_commit() {
    asm volatile("cp.async.commit_group;" ::: "memory");
}
template <int N>
__device__ __forceinline__ void cp_wait() {
    asm volatile("cp.async.wait_group %0;" :: "n"(N) : "memory");
}
__device__ __forceinline__ void ldm_x4(uint32_t* r, uint32_t addr) {
    asm volatile("ldmatrix.sync.aligned.m8n8.x4.shared.b16 {%0,%1,%2,%3}, [%4];"
                 : "=r"(r[0]), "=r"(r[1]), "=r"(r[2]), "=r"(r[3]) : "r"(addr));
}
__device__ __forceinline__ void mma16816(float* d, const uint32_t* a,
                                         uint32_t b0, uint32_t b1) {
    asm volatile(
        "mma.sync.aligned.m16n8k16.row.col.f32.bf16.bf16.f32 "
        "{%0,%1,%2,%3}, {%4,%5,%6,%7}, {%8,%9}, {%0,%1,%2,%3};"
        : "+f"(d[0]), "+f"(d[1]), "+f"(d[2]), "+f"(d[3])
        : "r"(a[0]), "r"(a[1]), "r"(a[2]), "r"(a[3]), "r"(b0), "r"(b1));
}

// Permuted conflict-free smem layout for one 128x32 bf16 tile (8 KB):
// atom = 8 rows x 16B (one k8 chunk) stored contiguously (128 B).
__device__ __forceinline__ uint32_t tile_off(int row, int kc) {
    return (uint32_t)((((row >> 3) * 4 + kc) << 7) + ((row & 7) << 4));
}

// ---------------------------------------------------------------------------
// Probe + repack (dtype-robust weight ingestion)
// ---------------------------------------------------------------------------
__global__ void probe_mode(const int* __restrict__ w)
{
    if (threadIdx.x == 0 && blockIdx.x == 0) {
        int ok = 0;
        for (int i = 0; i < 256; i++) {
            const int v = w[i];
            if (v >= -128 && v <= 127) ok++;
        }
        g_mode = (ok >= 250) ? 1 : 0;
    }
}
__global__ __launch_bounds__(256) void repack_w(
    const void* __restrict__ in, int8_t* __restrict__ out, long n)
{
    const int mode = g_mode;
    const long stride = (long)gridDim.x * blockDim.x;
    for (long i = (long)blockIdx.x * blockDim.x + threadIdx.x; i < n; i += stride) {
        if (mode) out[i] = (int8_t)((const int*)in)[i];
        else      out[i] = ((const int8_t*)in)[i];
    }
}

// ---------------------------------------------------------------------------
// Dequant Q4_0 + split into bf16 hi/lo.
// ---------------------------------------------------------------------------
__global__ __launch_bounds__(256) void dequant_split_w(
    const int8_t* __restrict__ w8, const float* __restrict__ sc,
    bf16* __restrict__ wh, bf16* __restrict__ wl, long n)
{
    const long stride = (long)gridDim.x * blockDim.x;
    for (long f = (long)blockIdx.x * blockDim.x + threadIdx.x; f < n; f += stride) {
        const long r = f >> 7;
        const int  q = (int)(f & 127);
        const int8_t b = w8[r * 64 + (q & 63)];
        const int nib = (q < 64) ? (b >> 4) : (((int8_t)(b << 4)) >> 4);
        const float v = (float)nib * sc[f >> 6];
        const bf16 hi = __float2bfloat16(v);
        wh[f] = hi;
        wl[f] = __float2bfloat16(v - __bfloat162float(hi));
    }
}

// Generic fp32 -> bf16 hi/lo split
__global__ __launch_bounds__(256) void split_f32(
    const float* __restrict__ src, bf16* __restrict__ hi, bf16* __restrict__ lo, long n)
{
    const long stride = (long)gridDim.x * blockDim.x;
    for (long i = (long)blockIdx.x * blockDim.x + threadIdx.x; i < n; i += stride) {
        const float v = src[i];
        const bf16 h = __float2bfloat16(v);
        hi[i] = h;
        lo[i] = __float2bfloat16(v - __bfloat162float(h));
    }
}

// ---------------------------------------------------------------------------
// RoPE (rotate-half) + optional scale + bf16 split.  x laid out [S, nh, HD].
// ---------------------------------------------------------------------------
__global__ __launch_bounds__(256) void rope_split(
    const float* __restrict__ x, const float* __restrict__ cosb,
    const float* __restrict__ sinb, bf16* __restrict__ oh, bf16* __restrict__ ol,
    int nheads, float scale)
{
    const long total = (long)SEQ * nheads * 64;
    long idx = (long)blockIdx.x * blockDim.x + threadIdx.x;
    if (idx >= total) return;
    const int d = (int)(idx & 63);
    const int h = (int)((idx >> 6) % nheads);
    const int s = (int)(idx / ((long)64 * nheads));
    const size_t base = (size_t)s * nheads * HD + h * HD + d;
    const float c  = cosb[s * 64 + d];
    const float sn = sinb[s * 64 + d];
    const float lo = x[base];
    const float hi = x[base + 64];
    const float r0 = (lo * c - hi * sn) * scale;
    const float r1 = (hi * c + lo * sn) * scale;
    bf16 h0 = __float2bfloat16(r0);
    bf16 h1 = __float2bfloat16(r1);
    oh[base]      = h0;
    ol[base]      = __float2bfloat16(r0 - __bfloat162float(h0));
    oh[base + 64] = h1;
    ol[base + 64] = __float2bfloat16(r1 - __bfloat162float(h1));
}

// ---------------------------------------------------------------------------
// Transpose V + split: vt[kv][d][s] = xv[s][kv*HD + d]
// ---------------------------------------------------------------------------
__global__ __launch_bounds__(256) void vtrans_split(
    const float* __restrict__ xv, bf16* __restrict__ vh, bf16* __restrict__ vl)
{
    const long total = (long)NKV * HD * SEQ;
    long idx = (long)blockIdx.x * blockDim.x + threadIdx.x;
    if (idx >= total) return;
    const int s  = (int)(idx % SEQ);
    const int d  = (int)((idx / SEQ) % HD);
    const int kv = (int)(idx / ((long)SEQ * HD));
    const float v = xv[(size_t)s * KVD + kv * HD + d];
    const bf16 h = __float2bfloat16(v);
    vh[idx] = h;
    vl[idx] = __float2bfloat16(v - __bfloat162float(h));
}

// ---------------------------------------------------------------------------
// Causal row softmax: fp32 scores -> bf16 hi/lo probs, zero-filled to the
// next 128 boundary (exactly the region the PV GEMM reads).
// ---------------------------------------------------------------------------
__global__ __launch_bounds__(128) void softmax_split(
    const float* __restrict__ sc, bf16* __restrict__ ph, bf16* __restrict__ pl)
{
    const int row = blockIdx.x;          // h*SEQ + q
    const int q   = row & (SEQ - 1);
    const float* p = sc + (size_t)row * SEQ;
    bf16* oh = ph + (size_t)row * SEQ;
    bf16* ol = pl + (size_t)row * SEQ;
    const int len  = q + 1;
    const int zend = ((q >> 7) + 1) << 7;
    const int tid  = threadIdx.x;

    __shared__ float red[4];

    float m = -1e30f;
    for (int k = tid; k < len; k += 128) m = fmaxf(m, p[k]);
#pragma unroll
    for (int o = 16; o > 0; o >>= 1) m = fmaxf(m, __shfl_xor_sync(0xffffffffu, m, o));
    if ((tid & 31) == 0) red[tid >> 5] = m;
    __syncthreads();
    m = fmaxf(fmaxf(red[0], red[1]), fmaxf(red[2], red[3]));
    __syncthreads();

    float sum = 0.0f;
    for (int k = tid; k < len; k += 128) sum += __expf(p[k] - m);
#pragma unroll
    for (int o = 16; o > 0; o >>= 1) sum += __shfl_xor_sync(0xffffffffu, sum, o);
    if ((tid & 31) == 0) red[tid >> 5] = sum;
    __syncthreads();
    sum = red[0] + red[1] + red[2] + red[3];

    const float inv = 1.0f / sum;
    for (int k = tid; k < len; k += 128) {
        const float v = __expf(p[k] - m) * inv;
        const bf16 h = __float2bfloat16(v);
        oh[k] = h;
        ol[k] = __float2bfloat16(v - __bfloat162float(h));
    }
    const bf16 z = __float2bfloat16(0.0f);
    for (int k = len + tid; k < zend; k += 128) { oh[k] = z; ol[k] = z; }
}

// ---------------------------------------------------------------------------
// mma.sync bf16 split-precision NT GEMM, v2.
//   C[m][n] = alpha * sum_k (Ah+Al)[m][k] * (Bh+Bl)[n][k]
// CTA tile 128x128, BK=32, 3-stage cp.async pipeline, 128 threads.
// 4 warps in a 2x2 grid, 64x64 per warp (4 m16 x 8 n8 fragments).
// head h = blockIdx.z; A += h*a_hs, B += (h/b_div)*b_hs, C += h*c_hs.
// causal==1: skip tile if n0 > m0+127.  causal==2: K limited to m0+128.
// ---------------------------------------------------------------------------
#define GS_TILE_BYTES  8192                 // one 128x32 bf16 tile
#define GS_STAGE_BYTES (4 * GS_TILE_BYTES)  // Ah, Al, Bh, Bl
#define GS_STAGES      3
#define GS_SMEM_TOTAL  (GS_STAGES * GS_STAGE_BYTES)   // 96 KB

__global__ __launch_bounds__(128, 2) void gemm_bf16s(
    const bf16* __restrict__ Ah, const bf16* __restrict__ Al,
    const bf16* __restrict__ Bh, const bf16* __restrict__ Bl,
    float* __restrict__ Cb,
    int K, int lda, int ldb, int ldc,
    long a_hs, long b_hs, int b_div, long c_hs,
    float alpha, int causal)
{
    const int m0 = blockIdx.y * 128;
    const int n0 = blockIdx.x * 128;
    if (causal == 1 && n0 > m0 + 127) return;

    extern __shared__ char smem[];
    const uint32_t sb = smem_u32(smem);
    const int tid  = threadIdx.x;
    const int wid  = tid >> 5;
    const int lane = tid & 31;
    const int h = blockIdx.z;

    const bf16* ah = Ah + (long)h * a_hs;
    const bf16* al = Al + (long)h * a_hs;
    const bf16* bh = Bh + (long)(h / b_div) * b_hs;
    const bf16* bl = Bl + (long)(h / b_div) * b_hs;
    float* C = Cb + (long)h * c_hs;

    const int kmax = (causal == 2) ? min(K, m0 + 128) : K;
    const int NC = kmax >> 5;

    const int wm = (wid & 1) * 64;   // warp m-offset
    const int wn = (wid >> 1) * 64;  // warp n-offset

    float acc[4][8][4];
#pragma unroll
    for (int i = 0; i < 4; i++)
#pragma unroll
        for (int j = 0; j < 8; j++)
#pragma unroll
            for (int v = 0; v < 4; v++) acc[i][j][v] = 0.0f;

    // loader: 128 threads, each thread owns one row; 4 k-chunks x 4 arrays
    auto load_stage = [&](int c) {
        const int k0 = c << 5;
        const uint32_t st = sb + (uint32_t)(c % GS_STAGES) * GS_STAGE_BYTES;
        const bf16* pa_h = ah + (size_t)(m0 + tid) * lda + k0;
        const bf16* pa_l = al + (size_t)(m0 + tid) * lda + k0;
        const bf16* pb_h = bh + (size_t)(n0 + tid) * ldb + k0;
        const bf16* pb_l = bl + (size_t)(n0 + tid) * ldb + k0;
#pragma unroll
        for (int kc = 0; kc < 4; kc++) {
            const uint32_t off = tile_off(tid, kc);
            cp16(st + 0 * GS_TILE_BYTES + off, pa_h + kc * 8);
            cp16(st + 1 * GS_TILE_BYTES + off, pa_l + kc * 8);
            cp16(st + 2 * GS_TILE_BYTES + off, pb_h + kc * 8);
            cp16(st + 3 * GS_TILE_BYTES + off, pb_l + kc * 8);
        }
        cp_commit();
    };

    load_stage(0);
    if (NC > 1) load_stage(1);

    const int lrow16 = lane & 15;
    const int lhi    = lane >> 4;

    for (int c = 0; c < NC; c++) {
        if (c + 1 < NC) cp_wait<1>();
        else            cp_wait<0>();
        __syncthreads();

        const uint32_t st = sb + (uint32_t)(c % GS_STAGES) * GS_STAGE_BYTES;

#pragma unroll
        for (int kb2 = 0; kb2 < 2; kb2++) {
            const int kcb = kb2 * 2;
            uint32_t afh[4][4], afl[4][4];
#pragma unroll
            for (int mt = 0; mt < 4; mt++) {
                const uint32_t off = tile_off(wm + mt * 16 + lrow16, kcb + lhi);
                ldm_x4(afh[mt], st + 0 * GS_TILE_BYTES + off);
                ldm_x4(afl[mt], st + 1 * GS_TILE_BYTES + off);
            }
#pragma unroll
            for (int g = 0; g < 4; g++) {
                const uint32_t boff = tile_off(wn + g * 16 + lrow16, kcb + lhi);
                uint32_t bhf[4], blf[4];
                ldm_x4(bhf, st + 2 * GS_TILE_BYTES + boff);
                ldm_x4(blf, st + 3 * GS_TILE_BYTES + boff);
#pragma unroll
                for (int mt = 0; mt < 4; mt++) {
#pragma unroll
                    for (int sub = 0; sub < 2; sub++) {
                        float* d = acc[mt][g * 2 + sub];
                        mma16816(d, afh[mt], bhf[sub], bhf[sub + 2]); // hi*hi
                        mma16816(d, afh[mt], blf[sub], blf[sub + 2]); // hi*lo
                        mma16816(d, afl[mt], bhf[sub], bhf[sub + 2]); // lo*hi
                    }
                }
            }
        }
        // 3-stage ring: stage (c+2)%3 was last read in iter c-1, and all warps
        // have passed this iteration's barrier, so overwrite is safe.
        if (c + 2 < NC) load_stage(c + 2);
    }

    // ---- epilogue ----
#pragma unroll
    for (int mt = 0; mt < 4; mt++) {
        const int mrow = m0 + wm + mt * 16 + (lane >> 2);
#pragma unroll
        for (int g = 0; g < 4; g++) {
#pragma unroll
            for (int sub = 0; sub < 2; sub++) {
                const float* d = acc[mt][g * 2 + sub];
                const int n = n0 + wn + g * 16 + sub * 8 + (lane & 3) * 2;
                float2 v0 = make_float2(d[0] * alpha, d[1] * alpha);
                float2 v1 = make_float2(d[2] * alpha, d[3] * alpha);
                *(float2*)(C + (size_t)mrow * ldc + n)       = v0;
                *(float2*)(C + (size_t)(mrow + 8) * ldc + n) = v1;
            }
        }
    }
}

// ---------------------------------------------------------------------------
// Launch
// ---------------------------------------------------------------------------
extern "C" void kernel_launch(void* const* d_in, const int* in_sizes, int n_in,
                              void* d_out, int out_size)
{
    (void)in_sizes; (void)n_in; (void)out_size;
    const float* x    = (const float*)d_in[0];
    const void*  wq   = d_in[1];
    const float* sq   = (const float*)d_in[2];
    const void*  wk   = d_in[3];
    const float* sk   = (const float*)d_in[4];
    const void*  wv   = d_in[5];
    const float* sv   = (const float*)d_in[6];
    const void*  wo   = d_in[7];
    const float* so   = (const float*)d_in[8];
    const float* cosb = (const float*)d_in[9];
    const float* sinb = (const float*)d_in[10];
    float* out = (float*)d_out;

    float *xq, *xk, *xv, *sc, *att;
    bf16 *xh, *xl, *qh, *ql, *kh, *kl, *vth, *vtl, *ath, *atl, *ph, *pl;
    bf16 *wqh, *wql, *wkh, *wkl, *wvh, *wvl, *woh, *wol;
    int8_t *wq8, *wk8, *wv8, *wo8;

    cudaGetSymbolAddress((void**)&xq,  g_xq);
    cudaGetSymbolAddress((void**)&xk,  g_xk);
    cudaGetSymbolAddress((void**)&xv,  g_xv);
    cudaGetSymbolAddress((void**)&sc,  g_sc);
    cudaGetSymbolAddress((void**)&att, g_att);
    cudaGetSymbolAddress((void**)&xh,  g_xh);   cudaGetSymbolAddress((void**)&xl,  g_xl);
    cudaGetSymbolAddress((void**)&qh,  g_qh);   cudaGetSymbolAddress((void**)&ql,  g_ql);
    cudaGetSymbolAddress((void**)&kh,  g_kh);   cudaGetSymbolAddress((void**)&kl,  g_kl);
    cudaGetSymbolAddress((void**)&vth, g_vth);  cudaGetSymbolAddress((void**)&vtl, g_vtl);
    cudaGetSymbolAddress((void**)&ath, g_ath);  cudaGetSymbolAddress((void**)&atl, g_atl);
    cudaGetSymbolAddress((void**)&ph,  g_ph);   cudaGetSymbolAddress((void**)&pl,  g_pl);
    cudaGetSymbolAddress((void**)&wqh, g_wqh);  cudaGetSymbolAddress((void**)&wql, g_wql);
    cudaGetSymbolAddress((void**)&wkh, g_wkh);  cudaGetSymbolAddress((void**)&wkl, g_wkl);
    cudaGetSymbolAddress((void**)&wvh, g_wvh);  cudaGetSymbolAddress((void**)&wvl, g_wvl);
    cudaGetSymbolAddress((void**)&woh, g_woh);  cudaGetSymbolAddress((void**)&wol, g_wol);
    cudaGetSymbolAddress((void**)&wq8, g_wq8);  cudaGetSymbolAddress((void**)&wk8, g_wk8);
    cudaGetSymbolAddress((void**)&wv8, g_wv8);  cudaGetSymbolAddress((void**)&wo8, g_wo8);

    cudaFuncSetAttribute(gemm_bf16s, cudaFuncAttributeMaxDynamicSharedMemorySize,
                         GS_SMEM_TOTAL);

    const dim3 blk(256);
    const dim3 gblk(128);
    const long nq = (long)DM * DM / 2;
    const long nk = (long)KVD * DM / 2;

    // Launch order chosen so ncu (-s 5 -c 1) profiles launch #6 = q-proj GEMM.
    probe_mode<<<1, 32>>>((const int*)wq);                                  // 1
    repack_w<<<1024, blk>>>(wq, wq8, nq);                                   // 2
    dequant_split_w<<<2048, blk>>>(wq8, sq, wqh, wql, (long)DM * DM);       // 3
    split_f32<<<2048, blk>>>(x, xh, xl, (long)SEQ * DM);                    // 4
    repack_w<<<1024, blk>>>(wk, wk8, nk);                                   // 5
    gemm_bf16s<<<dim3(DM / 128, SEQ / 128, 1), gblk, GS_SMEM_TOTAL>>>(      // 6 (ncu)
        xh, xl, wqh, wql, xq, DM, DM, DM, DM, 0, 0, 1, 0, 1.0f, 0);

    repack_w<<<1024, blk>>>(wv, wv8, nk);
    repack_w<<<1024, blk>>>(wo, wo8, nq);
    dequant_split_w<<<2048, blk>>>(wk8, sk, wkh, wkl, (long)KVD * DM);
    dequant_split_w<<<2048, blk>>>(wv8, sv, wvh, wvl, (long)KVD * DM);
    dequant_split_w<<<2048, blk>>>(wo8, so, woh, wol, (long)DM * DM);

    gemm_bf16s<<<dim3(KVD / 128, SEQ / 128, 1), gblk, GS_SMEM_TOTAL>>>(
        xh, xl, wkh, wkl, xk, DM, DM, DM, KVD, 0, 0, 1, 0, 1.0f, 0);
    gemm_bf16s<<<dim3(KVD / 128, SEQ / 128, 1), gblk, GS_SMEM_TOTAL>>>(
        xh, xl, wvh, wvl, xv, DM, DM, DM, KVD, 0, 0, 1, 0, 1.0f, 0);

    rope_split<<<(SEQ * NH  * 64 + 255) / 256, blk>>>(xq, cosb, sinb, qh, ql, NH,
                                                      0.08838834764831843f);
    rope_split<<<(SEQ * NKV * 64 + 255) / 256, blk>>>(xk, cosb, sinb, kh, kl, NKV, 1.0f);
    vtrans_split<<<(NKV * HD * SEQ + 255) / 256, blk>>>(xv, vth, vtl);

    gemm_bf16s<<<dim3(SEQ / 128, SEQ / 128, NH), gblk, GS_SMEM_TOTAL>>>(
        qh, ql, kh, kl, sc, HD, DM, KVD, SEQ,
        (long)HD, (long)HD, NH / NKV, (long)SEQ * SEQ, 1.0f, 1);

    softmax_split<<<NH * SEQ, 128>>>(sc, ph, pl);

    gemm_bf16s<<<dim3(HD / 128, SEQ / 128, NH), gblk, GS_SMEM_TOTAL>>>(
        ph, pl, vth, vtl, att, SEQ, SEQ, SEQ, DM,
        (long)SEQ * SEQ, (long)HD * SEQ, NH / NKV, (long)HD, 1.0f, 2);

    split_f32<<<2048, blk>>>(att, ath, atl, (long)SEQ * DM);
    gemm_bf16s<<<dim3(DM / 128, SEQ / 128, 1), gblk, GS_SMEM_TOTAL>>>(
        ath, atl, woh, wol, out, DM, DM, DM, DM, 0, 0, 1, 0, 1.0f, 0);
}

// round 6
// speedup vs baseline: 2.2507x; 1.3157x over previous
#include <cuda_runtime.h>
#include <cuda_fp16.h>
#include <cstdint>

// ---------------------------------------------------------------------------
// Problem constants
// ---------------------------------------------------------------------------
#define SEQ   2048
#define DM    4096
#define NH    32
#define NKV   8
#define HD    128
#define KVD   (NKV * HD)   // 1024

typedef __half h16;

// ---------------------------------------------------------------------------
// Device-global scratch (allocation-free rule)
// ---------------------------------------------------------------------------
__device__ float g_xq[SEQ * DM];
__device__ float g_xk[SEQ * KVD];
__device__ float g_xv[SEQ * KVD];
__device__ float g_sc[(size_t)NH * SEQ * SEQ];     // fp32 scores
__device__ float g_att[SEQ * DM];

// fp16 operands: score path split (hi/lo), value path plain
__device__ __align__(16) h16 g_xh [SEQ * DM],  g_xl [SEQ * DM];
__device__ __align__(16) h16 g_qh [SEQ * DM],  g_ql [SEQ * DM];
__device__ __align__(16) h16 g_kh [SEQ * KVD], g_kl [SEQ * KVD];
__device__ __align__(16) h16 g_vth[NKV * HD * SEQ];              // plain
__device__ __align__(16) h16 g_ath[SEQ * DM];                    // plain
__device__ __align__(16) h16 g_ph [(size_t)NH * SEQ * SEQ];      // plain probs
__device__ __align__(16) h16 g_wqh[DM * DM],   g_wql[DM * DM];   // split
__device__ __align__(16) h16 g_wkh[KVD * DM],  g_wkl[KVD * DM];  // split
__device__ __align__(16) h16 g_wvh[KVD * DM];                    // plain
__device__ __align__(16) h16 g_woh[DM * DM];                     // plain

// canonical int8 packed weights
__device__ int8_t g_wq8[DM * DM / 2];
__device__ int8_t g_wk8[KVD * DM / 2];
__device__ int8_t g_wv8[KVD * DM / 2];
__device__ int8_t g_wo8[DM * DM / 2];
__device__ int    g_mode;

// ---------------------------------------------------------------------------
// PTX helpers (base sm_103 ISA: cp.async / ldmatrix / mma.sync)
// ---------------------------------------------------------------------------
__device__ __forceinline__ uint32_t smem_u32(const void* p) {
    uint32_t a;
    asm("{ .reg .u64 t; cvta.to.shared.u64 t, %1; cvt.u32.u64 %0, t; }" : "=r"(a) : "l"(p));
    return a;
}
__device__ __forceinline__ void cp16(uint32_t dst, const void* src) {
    asm volatile("cp.async.cg.shared.global [%0], [%1], 16;" :: "r"(dst), "l"(src) : "memory");
}
__device__ __forceinline__ void cp_commit() {
    asm volatile("cp.async.commit_group;" ::: "memory");
}
template <int N>
__device__ __forceinline__ void cp_wait() {
    asm volatile("cp.async.wait_group %0;" :: "n"(N) : "memory");
}
__device__ __forceinline__ void ldm_x4(uint32_t* r, uint32_t addr) {
    asm volatile("ldmatrix.sync.aligned.m8n8.x4.shared.b16 {%0,%1,%2,%3}, [%4];"
                 : "=r"(r[0]), "=r"(r[1]), "=r"(r[2]), "=r"(r[3]) : "r"(addr));
}
// fp16 MMA, fp32 accumulate
__device__ __forceinline__ void mma_f32(float* d, const uint32_t* a,
                                        uint32_t b0, uint32_t b1) {
    asm volatile(
        "mma.sync.aligned.m16n8k16.row.col.f32.f16.f16.f32 "
        "{%0,%1,%2,%3}, {%4,%5,%6,%7}, {%8,%9}, {%0,%1,%2,%3};"
        : "+f"(d[0]), "+f"(d[1]), "+f"(d[2]), "+f"(d[3])
        : "r"(a[0]), "r"(a[1]), "r"(a[2]), "r"(a[3]), "r"(b0), "r"(b1));
}
// fp16 MMA, fp16 accumulate (for small cross terms)
__device__ __forceinline__ void mma_f16(uint32_t* d, const uint32_t* a,
                                        uint32_t b0, uint32_t b1) {
    asm volatile(
        "mma.sync.aligned.m16n8k16.row.col.f16.f16.f16.f16 "
        "{%0,%1}, {%2,%3,%4,%5}, {%6,%7}, {%0,%1};"
        : "+r"(d[0]), "+r"(d[1])
        : "r"(a[0]), "r"(a[1]), "r"(a[2]), "r"(a[3]), "r"(b0), "r"(b1));
}

// Permuted conflict-free smem layout for one 128x32 fp16 tile (8 KB):
// atom = 8 rows x 16B (one k8 chunk) stored contiguously (128 B).
__device__ __forceinline__ uint32_t tile_off(int row, int kc) {
    return (uint32_t)((((row >> 3) * 4 + kc) << 7) + ((row & 7) << 4));
}

// ---------------------------------------------------------------------------
// Probe + repack (dtype-robust weight ingestion)
// ---------------------------------------------------------------------------
__global__ void probe_mode(const int* __restrict__ w)
{
    if (threadIdx.x == 0 && blockIdx.x == 0) {
        int ok = 0;
        for (int i = 0; i < 256; i++) {
            const int v = w[i];
            if (v >= -128 && v <= 127) ok++;
        }
        g_mode = (ok >= 250) ? 1 : 0;
    }
}
__global__ __launch_bounds__(256) void repack_w(
    const void* __restrict__ in, int8_t* __restrict__ out, long n)
{
    const int mode = g_mode;
    const long stride = (long)gridDim.x * blockDim.x;
    for (long i = (long)blockIdx.x * blockDim.x + threadIdx.x; i < n; i += stride) {
        if (mode) out[i] = (int8_t)((const int*)in)[i];
        else      out[i] = ((const int8_t*)in)[i];
    }
}

// ---------------------------------------------------------------------------
// Dequant Q4_0 -> fp16 split (hi/lo) or plain
// ---------------------------------------------------------------------------
__global__ __launch_bounds__(256) void dequant_split_w(
    const int8_t* __restrict__ w8, const float* __restrict__ sc,
    h16* __restrict__ wh, h16* __restrict__ wl, long n)
{
    const long stride = (long)gridDim.x * blockDim.x;
    for (long f = (long)blockIdx.x * blockDim.x + threadIdx.x; f < n; f += stride) {
        const long r = f >> 7;
        const int  q = (int)(f & 127);
        const int8_t b = w8[r * 64 + (q & 63)];
        const int nib = (q < 64) ? (b >> 4) : (((int8_t)(b << 4)) >> 4);
        const float v = (float)nib * sc[f >> 6];
        const h16 hi = __float2half(v);
        wh[f] = hi;
        wl[f] = __float2half(v - __half2float(hi));
    }
}
__global__ __launch_bounds__(256) void dequant_plain_w(
    const int8_t* __restrict__ w8, const float* __restrict__ sc,
    h16* __restrict__ wh, long n)
{
    const long stride = (long)gridDim.x * blockDim.x;
    for (long f = (long)blockIdx.x * blockDim.x + threadIdx.x; f < n; f += stride) {
        const long r = f >> 7;
        const int  q = (int)(f & 127);
        const int8_t b = w8[r * 64 + (q & 63)];
        const int nib = (q < 64) ? (b >> 4) : (((int8_t)(b << 4)) >> 4);
        wh[f] = __float2half((float)nib * sc[f >> 6]);
    }
}

// Generic fp32 -> fp16 hi/lo split, and plain convert
__global__ __launch_bounds__(256) void split_f32(
    const float* __restrict__ src, h16* __restrict__ hi, h16* __restrict__ lo, long n)
{
    const long stride = (long)gridDim.x * blockDim.x;
    for (long i = (long)blockIdx.x * blockDim.x + threadIdx.x; i < n; i += stride) {
        const float v = src[i];
        const h16 h = __float2half(v);
        hi[i] = h;
        lo[i] = __float2half(v - __half2float(h));
    }
}
__global__ __launch_bounds__(256) void cvt_f32h(
    const float* __restrict__ src, h16* __restrict__ dst, long n)
{
    const long stride = (long)gridDim.x * blockDim.x;
    for (long i = (long)blockIdx.x * blockDim.x + threadIdx.x; i < n; i += stride)
        dst[i] = __float2half(src[i]);
}

// ---------------------------------------------------------------------------
// RoPE (rotate-half) + optional scale + fp16 split.  x laid out [S, nh, HD].
// ---------------------------------------------------------------------------
__global__ __launch_bounds__(256) void rope_split(
    const float* __restrict__ x, const float* __restrict__ cosb,
    const float* __restrict__ sinb, h16* __restrict__ oh, h16* __restrict__ ol,
    int nheads, float scale)
{
    const long total = (long)SEQ * nheads * 64;
    long idx = (long)blockIdx.x * blockDim.x + threadIdx.x;
    if (idx >= total) return;
    const int d = (int)(idx & 63);
    const int h = (int)((idx >> 6) % nheads);
    const int s = (int)(idx / ((long)64 * nheads));
    const size_t base = (size_t)s * nheads * HD + h * HD + d;
    const float c  = cosb[s * 64 + d];
    const float sn = sinb[s * 64 + d];
    const float lo = x[base];
    const float hi = x[base + 64];
    const float r0 = (lo * c - hi * sn) * scale;
    const float r1 = (hi * c + lo * sn) * scale;
    h16 h0 = __float2half(r0);
    h16 h1 = __float2half(r1);
    oh[base]      = h0;
    ol[base]      = __float2half(r0 - __half2float(h0));
    oh[base + 64] = h1;
    ol[base + 64] = __float2half(r1 - __half2float(h1));
}

// ---------------------------------------------------------------------------
// Transpose V to plain fp16: vt[kv][d][s] = xv[s][kv*HD + d]
// ---------------------------------------------------------------------------
__global__ __launch_bounds__(256) void vtrans_h(
    const float* __restrict__ xv, h16* __restrict__ vt)
{
    const long total = (long)NKV * HD * SEQ;
    long idx = (long)blockIdx.x * blockDim.x + threadIdx.x;
    if (idx >= total) return;
    const int s  = (int)(idx % SEQ);
    const int d  = (int)((idx / SEQ) % HD);
    const int kv = (int)(idx / ((long)SEQ * HD));
    vt[idx] = __float2half(xv[(size_t)s * KVD + kv * HD + d]);
}

// ---------------------------------------------------------------------------
// Causal row softmax: fp32 scores -> plain fp16 probs, zero-filled to the
// next 128 boundary (exactly the region the PV GEMM reads).
// ---------------------------------------------------------------------------
__global__ __launch_bounds__(128) void softmax_h(
    const float* __restrict__ sc, h16* __restrict__ ph)
{
    const int row = blockIdx.x;          // h*SEQ + q
    const int q   = row & (SEQ - 1);
    const float* p = sc + (size_t)row * SEQ;
    h16* oh = ph + (size_t)row * SEQ;
    const int len  = q + 1;
    const int zend = ((q >> 7) + 1) << 7;
    const int tid  = threadIdx.x;

    __shared__ float red[4];

    float m = -1e30f;
    for (int k = tid; k < len; k += 128) m = fmaxf(m, p[k]);
#pragma unroll
    for (int o = 16; o > 0; o >>= 1) m = fmaxf(m, __shfl_xor_sync(0xffffffffu, m, o));
    if ((tid & 31) == 0) red[tid >> 5] = m;
    __syncthreads();
    m = fmaxf(fmaxf(red[0], red[1]), fmaxf(red[2], red[3]));
    __syncthreads();

    float sum = 0.0f;
    for (int k = tid; k < len; k += 128) sum += __expf(p[k] - m);
#pragma unroll
    for (int o = 16; o > 0; o >>= 1) sum += __shfl_xor_sync(0xffffffffu, sum, o);
    if ((tid & 31) == 0) red[tid >> 5] = sum;
    __syncthreads();
    sum = red[0] + red[1] + red[2] + red[3];

    const float inv = 1.0f / sum;
    for (int k = tid; k < len; k += 128)
        oh[k] = __float2half(__expf(p[k] - m) * inv);
    const h16 z = __float2half(0.0f);
    for (int k = len + tid; k < zend; k += 128) oh[k] = z;
}

// ---------------------------------------------------------------------------
// GEMM3: score-path split GEMM.
//   C = alpha * (Ah+Al)(Bh+Bl)^T : main term hi*hi in fp32 acc, cross terms
//   hi*lo + lo*hi in fp16 acc carried across the whole K loop.
// CTA tile 128x128, BK=32, 3-stage cp.async, 256 threads (8 warps, 4x2 grid,
// warp tile 32x64).  causal==1: skip tile if n0 > m0+127.
// ---------------------------------------------------------------------------
#define G_TILE 8192
#define G3_STAGE (4 * G_TILE)           // Ah, Al, Bh, Bl : 32 KB
#define G3_SMEM  (3 * G3_STAGE)         // 96 KB
#define G1_STAGE (2 * G_TILE)           // A, B : 16 KB
#define G1_SMEM  (3 * G1_STAGE)         // 48 KB

__global__ __launch_bounds__(256, 1) void gemm3(
    const h16* __restrict__ Ah, const h16* __restrict__ Al,
    const h16* __restrict__ Bh, const h16* __restrict__ Bl,
    float* __restrict__ Cb,
    int K, int lda, int ldb, int ldc,
    long a_hs, long b_hs, int b_div, long c_hs,
    float alpha, int causal)
{
    const int m0 = blockIdx.y * 128;
    const int n0 = blockIdx.x * 128;
    if (causal == 1 && n0 > m0 + 127) return;

    extern __shared__ char smem[];
    const uint32_t sb = smem_u32(smem);
    const int tid  = threadIdx.x;
    const int wid  = tid >> 5;
    const int lane = tid & 31;
    const int h = blockIdx.z;

    const h16* ah = Ah + (long)h * a_hs;
    const h16* al = Al + (long)h * a_hs;
    const h16* bh = Bh + (long)(h / b_div) * b_hs;
    const h16* bl = Bl + (long)(h / b_div) * b_hs;
    float* C = Cb + (long)h * c_hs;

    const int NC = K >> 5;

    const int wm = (wid & 3) * 32;   // warp m-offset (4 warps down)
    const int wn = (wid >> 2) * 64;  // warp n-offset (2 warps across)

    float    accf[2][8][4];
    uint32_t accc[2][8][2];
#pragma unroll
    for (int i = 0; i < 2; i++)
#pragma unroll
        for (int j = 0; j < 8; j++) {
#pragma unroll
            for (int v = 0; v < 4; v++) accf[i][j][v] = 0.0f;
            accc[i][j][0] = 0u; accc[i][j][1] = 0u;
        }

    // loader: 256 threads; pair = A-side or B-side (hi & lo), 4 k-chunks each
    const int lrow = tid & 127;
    const int pair = tid >> 7;
    auto load_stage = [&](int c) {
        const int k0 = c << 5;
        const uint32_t st = sb + (uint32_t)(c % 3) * G3_STAGE;
        const h16* s0;
        const h16* s1;
        uint32_t b0, b1;
        if (pair == 0) {
            s0 = ah + (size_t)(m0 + lrow) * lda + k0;
            s1 = al + (size_t)(m0 + lrow) * lda + k0;
            b0 = st; b1 = st + G_TILE;
        } else {
            s0 = bh + (size_t)(n0 + lrow) * ldb + k0;
            s1 = bl + (size_t)(n0 + lrow) * ldb + k0;
            b0 = st + 2 * G_TILE; b1 = st + 3 * G_TILE;
        }
#pragma unroll
        for (int kc = 0; kc < 4; kc++) {
            const uint32_t off = tile_off(lrow, kc);
            cp16(b0 + off, s0 + kc * 8);
            cp16(b1 + off, s1 + kc * 8);
        }
        cp_commit();
    };

    load_stage(0);
    if (NC > 1) load_stage(1);

    const int lrow16 = lane & 15;
    const int lhi    = lane >> 4;

    for (int c = 0; c < NC; c++) {
        if (c + 1 < NC) cp_wait<1>();
        else            cp_wait<0>();
        __syncthreads();

        const uint32_t st = sb + (uint32_t)(c % 3) * G3_STAGE;

#pragma unroll
        for (int kb2 = 0; kb2 < 2; kb2++) {
            const int kcb = kb2 * 2;
            uint32_t afh[2][4], afl[2][4];
#pragma unroll
            for (int mt = 0; mt < 2; mt++) {
                const uint32_t off = tile_off(wm + mt * 16 + lrow16, kcb + lhi);
                ldm_x4(afh[mt], st + 0 * G_TILE + off);
                ldm_x4(afl[mt], st + 1 * G_TILE + off);
            }
#pragma unroll
            for (int g = 0; g < 4; g++) {
                const uint32_t boff = tile_off(wn + g * 16 + lrow16, kcb + lhi);
                uint32_t bhf[4], blf[4];
                ldm_x4(bhf, st + 2 * G_TILE + boff);
                ldm_x4(blf, st + 3 * G_TILE + boff);
#pragma unroll
                for (int mt = 0; mt < 2; mt++) {
#pragma unroll
                    for (int sub = 0; sub < 2; sub++) {
                        mma_f32(accf[mt][g * 2 + sub], afh[mt], bhf[sub], bhf[sub + 2]);
                        mma_f16(accc[mt][g * 2 + sub], afh[mt], blf[sub], blf[sub + 2]);
                        mma_f16(accc[mt][g * 2 + sub], afl[mt], bhf[sub], bhf[sub + 2]);
                    }
                }
            }
        }
        if (c + 2 < NC) load_stage(c + 2);
    }

    // ---- epilogue: main(f32) + cross(f16) ----
#pragma unroll
    for (int mt = 0; mt < 2; mt++) {
        const int mrow = m0 + wm + mt * 16 + (lane >> 2);
#pragma unroll
        for (int g = 0; g < 4; g++) {
#pragma unroll
            for (int sub = 0; sub < 2; sub++) {
                const float* d = accf[mt][g * 2 + sub];
                const __half2 c0 = *(const __half2*)&accc[mt][g * 2 + sub][0];
                const __half2 c1 = *(const __half2*)&accc[mt][g * 2 + sub][1];
                const int n = n0 + wn + g * 16 + sub * 8 + (lane & 3) * 2;
                float2 v0 = make_float2((d[0] + __low2float(c0)) * alpha,
                                        (d[1] + __high2float(c0)) * alpha);
                float2 v1 = make_float2((d[2] + __low2float(c1)) * alpha,
                                        (d[3] + __high2float(c1)) * alpha);
                *(float2*)(C + (size_t)mrow * ldc + n)       = v0;
                *(float2*)(C + (size_t)(mrow + 8) * ldc + n) = v1;
            }
        }
    }
}

// ---------------------------------------------------------------------------
// GEMM1: value-path plain fp16 GEMM, fp32 acc.  Same tiling as gemm3.
// causal==2: K limited to m0+128 (PV).
// ---------------------------------------------------------------------------
__global__ __launch_bounds__(256, 2) void gemm1(
    const h16* __restrict__ Ab, const h16* __restrict__ Bb,
    float* __restrict__ Cb,
    int K, int lda, int ldb, int ldc,
    long a_hs, long b_hs, int b_div, long c_hs,
    float alpha, int causal)
{
    const int m0 = blockIdx.y * 128;
    const int n0 = blockIdx.x * 128;

    extern __shared__ char smem[];
    const uint32_t sb = smem_u32(smem);
    const int tid  = threadIdx.x;
    const int wid  = tid >> 5;
    const int lane = tid & 31;
    const int h = blockIdx.z;

    const h16* A = Ab + (long)h * a_hs;
    const h16* B = Bb + (long)(h / b_div) * b_hs;
    float* C = Cb + (long)h * c_hs;

    const int kmax = (causal == 2) ? min(K, m0 + 128) : K;
    const int NC = kmax >> 5;

    const int wm = (wid & 3) * 32;
    const int wn = (wid >> 2) * 64;

    float accf[2][8][4];
#pragma unroll
    for (int i = 0; i < 2; i++)
#pragma unroll
        for (int j = 0; j < 8; j++)
#pragma unroll
            for (int v = 0; v < 4; v++) accf[i][j][v] = 0.0f;

    const int lrow = tid & 127;
    const int arr  = tid >> 7;
    auto load_stage = [&](int c) {
        const int k0 = c << 5;
        const uint32_t st = sb + (uint32_t)(c % 3) * G1_STAGE;
        const h16* s0 = arr ? (B + (size_t)(n0 + lrow) * ldb + k0)
                            : (A + (size_t)(m0 + lrow) * lda + k0);
        const uint32_t b0 = st + (uint32_t)arr * G_TILE;
#pragma unroll
        for (int kc = 0; kc < 4; kc++)
            cp16(b0 + tile_off(lrow, kc), s0 + kc * 8);
        cp_commit();
    };

    load_stage(0);
    if (NC > 1) load_stage(1);

    const int lrow16 = lane & 15;
    const int lhi    = lane >> 4;

    for (int c = 0; c < NC; c++) {
        if (c + 1 < NC) cp_wait<1>();
        else            cp_wait<0>();
        __syncthreads();

        const uint32_t st = sb + (uint32_t)(c % 3) * G1_STAGE;

#pragma unroll
        for (int kb2 = 0; kb2 < 2; kb2++) {
            const int kcb = kb2 * 2;
            uint32_t af[2][4];
#pragma unroll
            for (int mt = 0; mt < 2; mt++)
                ldm_x4(af[mt], st + tile_off(wm + mt * 16 + lrow16, kcb + lhi));
#pragma unroll
            for (int g = 0; g < 4; g++) {
                uint32_t bf[4];
                ldm_x4(bf, st + G_TILE + tile_off(wn + g * 16 + lrow16, kcb + lhi));
#pragma unroll
                for (int mt = 0; mt < 2; mt++) {
#pragma unroll
                    for (int sub = 0; sub < 2; sub++)
                        mma_f32(accf[mt][g * 2 + sub], af[mt], bf[sub], bf[sub + 2]);
                }
            }
        }
        if (c + 2 < NC) load_stage(c + 2);
    }

#pragma unroll
    for (int mt = 0; mt < 2; mt++) {
        const int mrow = m0 + wm + mt * 16 + (lane >> 2);
#pragma unroll
        for (int g = 0; g < 4; g++) {
#pragma unroll
            for (int sub = 0; sub < 2; sub++) {
                const float* d = accf[mt][g * 2 + sub];
                const int n = n0 + wn + g * 16 + sub * 8 + (lane & 3) * 2;
                *(float2*)(C + (size_t)mrow * ldc + n) =
                    make_float2(d[0] * alpha, d[1] * alpha);
                *(float2*)(C + (size_t)(mrow + 8) * ldc + n) =
                    make_float2(d[2] * alpha, d[3] * alpha);
            }
        }
    }
}

// ---------------------------------------------------------------------------
// Launch
// ---------------------------------------------------------------------------
extern "C" void kernel_launch(void* const* d_in, const int* in_sizes, int n_in,
                              void* d_out, int out_size)
{
    (void)in_sizes; (void)n_in; (void)out_size;
    const float* x    = (const float*)d_in[0];
    const void*  wq   = d_in[1];
    const float* sq   = (const float*)d_in[2];
    const void*  wk   = d_in[3];
    const float* sk   = (const float*)d_in[4];
    const void*  wv   = d_in[5];
    const float* sv   = (const float*)d_in[6];
    const void*  wo   = d_in[7];
    const float* so   = (const float*)d_in[8];
    const float* cosb = (const float*)d_in[9];
    const float* sinb = (const float*)d_in[10];
    float* out = (float*)d_out;

    float *xq, *xk, *xv, *sc, *att;
    h16 *xh, *xl, *qh, *ql, *kh, *kl, *vth, *ath, *ph;
    h16 *wqh, *wql, *wkh, *wkl, *wvh, *woh;
    int8_t *wq8, *wk8, *wv8, *wo8;

    cudaGetSymbolAddress((void**)&xq,  g_xq);
    cudaGetSymbolAddress((void**)&xk,  g_xk);
    cudaGetSymbolAddress((void**)&xv,  g_xv);
    cudaGetSymbolAddress((void**)&sc,  g_sc);
    cudaGetSymbolAddress((void**)&att, g_att);
    cudaGetSymbolAddress((void**)&xh,  g_xh);   cudaGetSymbolAddress((void**)&xl,  g_xl);
    cudaGetSymbolAddress((void**)&qh,  g_qh);   cudaGetSymbolAddress((void**)&ql,  g_ql);
    cudaGetSymbolAddress((void**)&kh,  g_kh);   cudaGetSymbolAddress((void**)&kl,  g_kl);
    cudaGetSymbolAddress((void**)&vth, g_vth);
    cudaGetSymbolAddress((void**)&ath, g_ath);
    cudaGetSymbolAddress((void**)&ph,  g_ph);
    cudaGetSymbolAddress((void**)&wqh, g_wqh);  cudaGetSymbolAddress((void**)&wql, g_wql);
    cudaGetSymbolAddress((void**)&wkh, g_wkh);  cudaGetSymbolAddress((void**)&wkl, g_wkl);
    cudaGetSymbolAddress((void**)&wvh, g_wvh);
    cudaGetSymbolAddress((void**)&woh, g_woh);
    cudaGetSymbolAddress((void**)&wq8, g_wq8);  cudaGetSymbolAddress((void**)&wk8, g_wk8);
    cudaGetSymbolAddress((void**)&wv8, g_wv8);  cudaGetSymbolAddress((void**)&wo8, g_wo8);

    cudaFuncSetAttribute(gemm3, cudaFuncAttributeMaxDynamicSharedMemorySize, G3_SMEM);
    cudaFuncSetAttribute(gemm1, cudaFuncAttributeMaxDynamicSharedMemorySize, G1_SMEM);

    const dim3 blk(256);
    const long nq = (long)DM * DM / 2;
    const long nk = (long)KVD * DM / 2;

    // 0) ingest + prepare q-path, launch q-proj early (ncu target window)
    probe_mode<<<1, 32>>>((const int*)wq);
    repack_w<<<1024, blk>>>(wq, wq8, nq);
    dequant_split_w<<<2048, blk>>>(wq8, sq, wqh, wql, (long)DM * DM);
    split_f32<<<2048, blk>>>(x, xh, xl, (long)SEQ * DM);
    gemm3<<<dim3(DM / 128, SEQ / 128, 1), blk, G3_SMEM>>>(      // score path: q-proj
        xh, xl, wqh, wql, xq, DM, DM, DM, DM, 0, 0, 1, 0, 1.0f, 0);

    repack_w<<<1024, blk>>>(wk, wk8, nk);
    repack_w<<<1024, blk>>>(wv, wv8, nk);
    repack_w<<<1024, blk>>>(wo, wo8, nq);
    dequant_split_w<<<2048, blk>>>(wk8, sk, wkh, wkl, (long)KVD * DM);
    dequant_plain_w<<<2048, blk>>>(wv8, sv, wvh, (long)KVD * DM);
    dequant_plain_w<<<2048, blk>>>(wo8, so, woh, (long)DM * DM);

    // k-proj (score path, 3-term), v-proj (value path, 1-term)
    gemm3<<<dim3(KVD / 128, SEQ / 128, 1), blk, G3_SMEM>>>(
        xh, xl, wkh, wkl, xk, DM, DM, DM, KVD, 0, 0, 1, 0, 1.0f, 0);
    gemm1<<<dim3(KVD / 128, SEQ / 128, 1), blk, G1_SMEM>>>(
        xh, wvh, xv, DM, DM, DM, KVD, 0, 0, 1, 0, 1.0f, 0);

    // RoPE (+1/sqrt(HD) on q) -> fp16 splits; V transpose -> plain fp16
    rope_split<<<(SEQ * NH  * 64 + 255) / 256, blk>>>(xq, cosb, sinb, qh, ql, NH,
                                                      0.08838834764831843f);
    rope_split<<<(SEQ * NKV * 64 + 255) / 256, blk>>>(xk, cosb, sinb, kh, kl, NKV, 1.0f);
    vtrans_h<<<(NKV * HD * SEQ + 255) / 256, blk>>>(xv, vth);

    // scores = (q/sqrt(HD)) K^T  (3-term, lower-triangular tiles only)
    gemm3<<<dim3(SEQ / 128, SEQ / 128, NH), blk, G3_SMEM>>>(
        qh, ql, kh, kl, sc, HD, DM, KVD, SEQ,
        (long)HD, (long)HD, NH / NKV, (long)SEQ * SEQ, 1.0f, 1);

    // causal softmax -> plain fp16 probs
    softmax_h<<<NH * SEQ, 128>>>(sc, ph);

    // att = P V  (1-term, k-limited)
    gemm1<<<dim3(HD / 128, SEQ / 128, NH), blk, G1_SMEM>>>(
        ph, vth, att, SEQ, SEQ, SEQ, DM,
        (long)SEQ * SEQ, (long)HD * SEQ, NH / NKV, (long)HD, 1.0f, 2);

    // output projection (1-term)
    cvt_f32h<<<2048, blk>>>(att, ath, (long)SEQ * DM);
    gemm1<<<dim3(DM / 128, SEQ / 128, 1), blk, G1_SMEM>>>(
        ath, woh, out, DM, DM, DM, DM, 0, 0, 1, 0, 1.0f, 0);
}